// round 5
// baseline (speedup 1.0000x reference)
#include <cuda_runtime.h>
#include <cuda_bf16.h>
#include <cstdint>

// ============================================================================
// Problem constants
// ============================================================================
#define BATCH   8192
#define FDIM    64
#define NXC     82
#define NYC     67
#define PDIM    5494          // NXC*NYC
#define PPAD    5504          // 43 * 128, zero-padded
#define KCAT    192           // [Ah|Ah|Al] x [Wh|Wl|Wh] fused 3-pass split-bf16
#define TILE_M  128
#define TILE_N  128
#define PITCH_E 200           // smem row pitch in bf16 elems (400 B, conflict-free)
#define PITCH_B 400

// ============================================================================
// Scratch (device globals; no allocation allowed)
// ============================================================================
__device__ __align__(16) __nv_bfloat16 g_Acat[BATCH * KCAT];
__device__ __align__(16) __nv_bfloat16 g_Wcat[PPAD * KCAT];
__device__ __align__(16) float         g_bias[PPAD];

// ============================================================================
// Prep kernels: bf16 hi/lo split, K-concat, W row permutation, bias permute
// ============================================================================
__global__ void prep_A_kernel(const float* __restrict__ A) {
    int e = blockIdx.x * blockDim.x + threadIdx.x;
    if (e < BATCH * FDIM) {
        int m = e >> 6, f = e & 63;
        float v = A[e];
        __nv_bfloat16 h = __float2bfloat16(v);
        __nv_bfloat16 l = __float2bfloat16(v - __bfloat162float(h));
        __nv_bfloat16* row = g_Acat + (size_t)m * KCAT;
        row[f]       = h;   // pass 0: Ah * Wh
        row[64 + f]  = h;   // pass 1: Ah * Wl
        row[128 + f] = l;   // pass 2: Al * Wh
    }
}

__global__ void prep_W_kernel(const float* __restrict__ W, const float* __restrict__ b) {
    int e = blockIdx.x * blockDim.x + threadIdx.x;
    if (e < PPAD * FDIM) {
        int q = e >> 6, f = e & 63;     // q = x*67 + y (transpose folded in)
        float v = 0.0f;
        if (q < PDIM) {
            int x = q / NYC, y = q % NYC;
            v = W[(y * NXC + x) * FDIM + f];
        }
        __nv_bfloat16 h = __float2bfloat16(v);
        __nv_bfloat16 l = __float2bfloat16(v - __bfloat162float(h));
        __nv_bfloat16* row = g_Wcat + (size_t)q * KCAT;
        row[f]       = h;   // Wh
        row[64 + f]  = l;   // Wl
        row[128 + f] = h;   // Wh
        if (f == 0) {
            float bv = 0.0f;
            if (q < PDIM) {
                int x = q / NYC, y = q % NYC;
                bv = b[y * NXC + x];
            }
            g_bias[q] = bv;
        }
    }
}

// ============================================================================
// GEMM: C[8192,5504] = A_cat @ W_cat^T  (mma.sync m16n8k16 bf16, fp32 acc)
// CTA 128x128, 8 warps (4 along M x 2 along N), warp tile 32x64, K=192.
// ============================================================================
#define SM_A     0
#define SM_W     (TILE_M * PITCH_B)                 // 51200
#define SM_BIAS  (2 * TILE_M * PITCH_B)             // 102400
#define SMEM_BYTES (2 * TILE_M * PITCH_B + TILE_N * 4)  // 102912

__device__ __forceinline__ uint32_t smem_u32(const void* p) {
    uint32_t a;
    asm("{ .reg .u64 t; cvta.to.shared.u64 t, %1; cvt.u32.u64 %0, t; }"
        : "=r"(a) : "l"(p));
    return a;
}

__device__ __forceinline__ void ldm_x4(uint32_t& r0, uint32_t& r1,
                                       uint32_t& r2, uint32_t& r3, uint32_t addr) {
    asm volatile("ldmatrix.sync.aligned.m8n8.x4.shared.b16 {%0,%1,%2,%3}, [%4];"
                 : "=r"(r0), "=r"(r1), "=r"(r2), "=r"(r3) : "r"(addr));
}

__device__ __forceinline__ void mma16816(float* c, const uint32_t* a,
                                         uint32_t b0, uint32_t b1) {
    asm volatile(
        "mma.sync.aligned.m16n8k16.row.col.f32.bf16.bf16.f32 "
        "{%0,%1,%2,%3}, {%4,%5,%6,%7}, {%8,%9}, {%0,%1,%2,%3};"
        : "+f"(c[0]), "+f"(c[1]), "+f"(c[2]), "+f"(c[3])
        : "r"(a[0]), "r"(a[1]), "r"(a[2]), "r"(a[3]), "r"(b0), "r"(b1));
}

__global__ void __launch_bounds__(256, 2) gemm_kernel(float* __restrict__ out) {
    extern __shared__ char smem[];
    uint32_t sb = smem_u32(smem);
    int tid  = threadIdx.x;
    int lane = tid & 31;
    int wid  = tid >> 5;
    int wm   = wid & 3;        // warp row (0..3) -> 32 rows each
    int wn   = wid >> 2;       // warp col (0..1) -> 64 cols each
    int n0 = blockIdx.x * TILE_N;
    int m0 = blockIdx.y * TILE_M;

    // ---- Stage full K=192 tiles: 128 rows x 384B, padded pitch 400B ----
    // 24 x 16B chunks per row; 128 rows -> 3072 chunks per tile; 256 thr -> 12 ea.
    {
        const uint4* gA = (const uint4*)(g_Acat + (size_t)m0 * KCAT);
        const uint4* gW = (const uint4*)(g_Wcat + (size_t)n0 * KCAT);
        #pragma unroll
        for (int i = tid; i < TILE_M * 24; i += 256) {
            int r = i / 24, ch = i % 24;
            uint4 va = gA[r * 24 + ch];
            uint4 vw = gW[r * 24 + ch];
            *(uint4*)(smem + SM_A + r * PITCH_B + ch * 16) = va;
            *(uint4*)(smem + SM_W + r * PITCH_B + ch * 16) = vw;
        }
        if (tid < TILE_N)
            ((float*)(smem + SM_BIAS))[tid] = g_bias[n0 + tid];
    }
    __syncthreads();

    // ---- per-lane ldmatrix base addresses ----
    // A: matrices (rowblk, khalf): lanes 0-15 rows (lane&15), lanes 16-31 k+8
    uint32_t aBase = sb + SM_A
        + (uint32_t)(wm * 32 + (lane & 15)) * PITCH_B + ((lane >> 4) * 16);
    // W(B): m0: rows n..n+7 k0 | m1: rows n..n+7 k+8 | m2: rows n+8.. k0 | m3: +8 k+8
    uint32_t bBase = sb + SM_W
        + (uint32_t)(wn * 64 + ((lane >> 4) << 3) + (lane & 7)) * PITCH_B
        + (((lane >> 3) & 1) * 16);

    float c[2][8][4];
    #pragma unroll
    for (int mi = 0; mi < 2; mi++)
        #pragma unroll
        for (int ni = 0; ni < 8; ni++)
            #pragma unroll
            for (int r = 0; r < 4; r++) c[mi][ni][r] = 0.0f;

    // ---- mainloop: 12 k-steps of 16 ----
    #pragma unroll
    for (int ks = 0; ks < KCAT / 16; ks++) {
        uint32_t a[2][4];
        #pragma unroll
        for (int mi = 0; mi < 2; mi++)
            ldm_x4(a[mi][0], a[mi][1], a[mi][2], a[mi][3],
                   aBase + mi * 16 * PITCH_B + ks * 32);
        uint32_t b[4][4];
        #pragma unroll
        for (int nq = 0; nq < 4; nq++)
            ldm_x4(b[nq][0], b[nq][1], b[nq][2], b[nq][3],
                   bBase + nq * 16 * PITCH_B + ks * 32);
        #pragma unroll
        for (int mi = 0; mi < 2; mi++)
            #pragma unroll
            for (int ni = 0; ni < 8; ni++)
                mma16816(c[mi][ni], a[mi],
                         b[ni >> 1][(ni & 1) * 2], b[ni >> 1][(ni & 1) * 2 + 1]);
    }

    // ---- epilogue: +bias, direct float2 stores (pairs all-or-nothing) ----
    const float* sbias = (const float*)(smem + SM_BIAS);
    int g = lane >> 2, t = lane & 3;
    #pragma unroll
    for (int mi = 0; mi < 2; mi++) {
        int r0 = m0 + wm * 32 + mi * 16 + g;    // and r0+8
        #pragma unroll
        for (int ni = 0; ni < 8; ni++) {
            int lc = wn * 64 + ni * 8 + 2 * t;  // local col (even)
            int n  = n0 + lc;
            if (n < PDIM) {                      // PDIM even -> pair safe
                float b0 = sbias[lc], b1 = sbias[lc + 1];
                float2 v0 = {c[mi][ni][0] + b0, c[mi][ni][1] + b1};
                float2 v1 = {c[mi][ni][2] + b0, c[mi][ni][3] + b1};
                *(float2*)(out + (size_t)r0 * PDIM + n) = v0;
                *(float2*)(out + (size_t)(r0 + 8) * PDIM + n) = v1;
            }
        }
    }
}

// ============================================================================
// Launch
// ============================================================================
extern "C" void kernel_launch(void* const* d_in, const int* in_sizes, int n_in,
                              void* d_out, int out_size) {
    const float* A = (const float*)d_in[0];   // [8192, 64]
    const float* W = (const float*)d_in[1];   // [5494, 64]
    const float* b = (const float*)d_in[2];   // [5494]
    float* out = (float*)d_out;               // [8192, 82, 67, 1] contiguous

    cudaFuncSetAttribute(gemm_kernel,
                         cudaFuncAttributeMaxDynamicSharedMemorySize, SMEM_BYTES);

    prep_A_kernel<<<(BATCH * FDIM + 255) / 256, 256>>>(A);
    prep_W_kernel<<<(PPAD * FDIM + 255) / 256, 256>>>(W, b);

    dim3 grid(PPAD / TILE_N, BATCH / TILE_M);   // 43 x 64
    gemm_kernel<<<grid, 256, SMEM_BYTES>>>(out);
}

// round 6
// speedup vs baseline: 1.1671x; 1.1671x over previous
#include <cuda_runtime.h>
#include <cuda_bf16.h>
#include <cstdint>

// ============================================================================
// Problem constants
// ============================================================================
#define BATCH   8192
#define FDIM    64
#define NXC     82
#define NYC     67
#define PDIM    5494          // NXC*NYC
#define PPAD    5504          // 43 * 128, zero-padded
#define KCAT    192           // [Ah|Ah|Al] x [Wh|Wl|Wh] fused 3-pass split-bf16
#define TILE_N  128
#define MTILE   64            // rows per m-step
#define MSTEPS  8             // m-steps per CTA (grid.y=16 -> 16*8*64 = 8192)
#define PITCH   400           // smem row pitch bytes (384B data + 16B pad)

// ============================================================================
// Scratch (device globals; no allocation allowed)
// ============================================================================
__device__ __align__(16) __nv_bfloat16 g_Acat[BATCH * KCAT];
__device__ __align__(16) __nv_bfloat16 g_Wcat[PPAD * KCAT];
__device__ __align__(16) float         g_bias[PPAD];

// ============================================================================
// Fused prep: bf16 hi/lo split + K-concat + W row permutation + bias permute
// ============================================================================
__global__ void prep_kernel(const float* __restrict__ A,
                            const float* __restrict__ W,
                            const float* __restrict__ b) {
    int e = blockIdx.x * blockDim.x + threadIdx.x;
    if (e < BATCH * FDIM) {
        int m = e >> 6, f = e & 63;
        float v = A[e];
        __nv_bfloat16 h = __float2bfloat16(v);
        __nv_bfloat16 l = __float2bfloat16(v - __bfloat162float(h));
        __nv_bfloat16* row = g_Acat + (size_t)m * KCAT;
        row[f]       = h;   // pass 0: Ah * Wh
        row[64 + f]  = h;   // pass 1: Ah * Wl
        row[128 + f] = l;   // pass 2: Al * Wh
    } else {
        int e2 = e - BATCH * FDIM;
        if (e2 < PPAD * FDIM) {
            int q = e2 >> 6, f = e2 & 63;   // q = x*67 + y (transpose folded in)
            float v = 0.0f;
            if (q < PDIM) {
                int x = q / NYC, y = q % NYC;
                v = W[(y * NXC + x) * FDIM + f];
            }
            __nv_bfloat16 h = __float2bfloat16(v);
            __nv_bfloat16 l = __float2bfloat16(v - __bfloat162float(h));
            __nv_bfloat16* row = g_Wcat + (size_t)q * KCAT;
            row[f]       = h;   // Wh
            row[64 + f]  = l;   // Wl
            row[128 + f] = h;   // Wh
            if (f == 0) {
                float bv = 0.0f;
                if (q < PDIM) {
                    int x = q / NYC, y = q % NYC;
                    bv = b[y * NXC + x];
                }
                g_bias[q] = bv;
            }
        }
    }
}

// ============================================================================
// Helpers
// ============================================================================
__device__ __forceinline__ uint32_t smem_u32(const void* p) {
    uint32_t a;
    asm("{ .reg .u64 t; cvta.to.shared.u64 t, %1; cvt.u32.u64 %0, t; }"
        : "=r"(a) : "l"(p));
    return a;
}

__device__ __forceinline__ void cpasync16(uint32_t dst, const void* src) {
    asm volatile("cp.async.cg.shared.global [%0], [%1], 16;"
                 :: "r"(dst), "l"(src));
}
#define CP_COMMIT() asm volatile("cp.async.commit_group;" ::: "memory")
#define CP_WAIT(n)  asm volatile("cp.async.wait_group %0;" :: "n"(n) : "memory")

__device__ __forceinline__ void ldm_x4(uint32_t& r0, uint32_t& r1,
                                       uint32_t& r2, uint32_t& r3, uint32_t addr) {
    asm volatile("ldmatrix.sync.aligned.m8n8.x4.shared.b16 {%0,%1,%2,%3}, [%4];"
                 : "=r"(r0), "=r"(r1), "=r"(r2), "=r"(r3) : "r"(addr));
}

__device__ __forceinline__ void mma16816(float* c, const uint32_t* a,
                                         uint32_t b0, uint32_t b1) {
    asm volatile(
        "mma.sync.aligned.m16n8k16.row.col.f32.bf16.bf16.f32 "
        "{%0,%1,%2,%3}, {%4,%5,%6,%7}, {%8,%9}, {%0,%1,%2,%3};"
        : "+f"(c[0]), "+f"(c[1]), "+f"(c[2]), "+f"(c[3])
        : "r"(a[0]), "r"(a[1]), "r"(a[2]), "r"(a[3]), "r"(b0), "r"(b1));
}

// ============================================================================
// GEMM: persistent W tile, 2-stage cp.async pipeline over 8 m-tiles of 64.
// CTA tile 64x128 per m-step, 8 warps (2 along M x 4 along N), warp 32x32.
// ============================================================================
#define SM_W     0                           // 128*400 = 51200
#define SM_BIAS  51200                       // 512 B
#define SM_A0    51712                       // 64*400 = 25600
#define SM_A1    77312
#define SMEM_BYTES 102912

__global__ void __launch_bounds__(256, 2) gemm_kernel(float* __restrict__ out) {
    extern __shared__ char smem[];
    uint32_t sb = smem_u32(smem);
    int tid  = threadIdx.x;
    int lane = tid & 31;
    int wid  = tid >> 5;
    int wm   = wid & 1;        // warp row (0..1) -> 32 rows each
    int wn   = wid >> 1;       // warp col (0..3) -> 32 cols each
    int n0    = blockIdx.x * TILE_N;
    int mbase = blockIdx.y * MSTEPS;   // first m-tile index

    // ---- stage W tile (persistent) + bias, group 0 ----
    {
        const char* gW = (const char*)(g_Wcat + (size_t)n0 * KCAT);
        #pragma unroll
        for (int i = tid; i < TILE_N * 24; i += 256) {
            int r = i / 24, ch = i % 24;
            cpasync16(sb + SM_W + r * PITCH + ch * 16, gW + r * 384 + ch * 16);
        }
        if (tid < TILE_N)
            ((float*)(smem + SM_BIAS))[tid] = g_bias[n0 + tid];
    }
    CP_COMMIT();

    // ---- prologue: A tile 0, group 1 ----
    {
        const char* gA = (const char*)(g_Acat + (size_t)mbase * MTILE * KCAT);
        #pragma unroll
        for (int i = tid; i < MTILE * 24; i += 256) {
            int r = i / 24, ch = i % 24;
            cpasync16(sb + SM_A0 + r * PITCH + ch * 16, gA + r * 384 + ch * 16);
        }
    }
    CP_COMMIT();

    // ---- per-lane ldmatrix base addresses (A base recomputed per buffer) ----
    uint32_t aOff = (uint32_t)(wm * 32 + (lane & 15)) * PITCH + ((lane >> 4) * 16);
    uint32_t bBase = sb + SM_W
        + (uint32_t)(wn * 32 + ((lane >> 4) << 3) + (lane & 7)) * PITCH
        + (((lane >> 3) & 1) * 16);
    const float* sbias = (const float*)(smem + SM_BIAS);
    int g = lane >> 2, t = lane & 3;

    #pragma unroll 1
    for (int mt = 0; mt < MSTEPS; mt++) {
        uint32_t bufoff = (mt & 1) ? SM_A1 : SM_A0;

        // prefetch next A tile into the other buffer, then drain current stage
        if (mt < MSTEPS - 1) {
            uint32_t nbuf = (mt & 1) ? SM_A0 : SM_A1;
            const char* gA =
                (const char*)(g_Acat + (size_t)(mbase + mt + 1) * MTILE * KCAT);
            #pragma unroll
            for (int i = tid; i < MTILE * 24; i += 256) {
                int r = i / 24, ch = i % 24;
                cpasync16(sb + nbuf + r * PITCH + ch * 16, gA + r * 384 + ch * 16);
            }
            CP_COMMIT();
            CP_WAIT(1);          // current stage (and W) complete
        } else {
            CP_WAIT(0);
        }
        __syncthreads();

        // ---- compute 64x128 from smem ----
        float c[2][4][4];
        #pragma unroll
        for (int mi = 0; mi < 2; mi++)
            #pragma unroll
            for (int ni = 0; ni < 4; ni++)
                #pragma unroll
                for (int r = 0; r < 4; r++) c[mi][ni][r] = 0.0f;

        uint32_t aBase = sb + bufoff + aOff;
        #pragma unroll
        for (int ks = 0; ks < KCAT / 16; ks++) {
            uint32_t a[2][4];
            #pragma unroll
            for (int mi = 0; mi < 2; mi++)
                ldm_x4(a[mi][0], a[mi][1], a[mi][2], a[mi][3],
                       aBase + mi * 16 * PITCH + ks * 32);
            uint32_t b[2][4];
            #pragma unroll
            for (int nq = 0; nq < 2; nq++)
                ldm_x4(b[nq][0], b[nq][1], b[nq][2], b[nq][3],
                       bBase + nq * 16 * PITCH + ks * 32);
            #pragma unroll
            for (int mi = 0; mi < 2; mi++)
                #pragma unroll
                for (int ni = 0; ni < 4; ni++)
                    mma16816(c[mi][ni], a[mi],
                             b[ni >> 1][(ni & 1) * 2], b[ni >> 1][(ni & 1) * 2 + 1]);
        }

        // ---- epilogue: +bias, direct float2 stores ----
        int m0 = (mbase + mt) * MTILE;
        #pragma unroll
        for (int mi = 0; mi < 2; mi++) {
            int r0 = m0 + wm * 32 + mi * 16 + g;    // and r0+8
            #pragma unroll
            for (int ni = 0; ni < 4; ni++) {
                int lc = wn * 32 + ni * 8 + 2 * t;  // local col (even)
                int n  = n0 + lc;
                if (n < PDIM) {                      // PDIM even -> pair safe
                    float b0 = sbias[lc], b1 = sbias[lc + 1];
                    float2 v0 = {c[mi][ni][0] + b0, c[mi][ni][1] + b1};
                    float2 v1 = {c[mi][ni][2] + b0, c[mi][ni][3] + b1};
                    *(float2*)(out + (size_t)r0 * PDIM + n) = v0;
                    *(float2*)(out + (size_t)(r0 + 8) * PDIM + n) = v1;
                }
            }
        }
        __syncthreads();   // all warps done reading bufoff before it is refilled
    }
}

// ============================================================================
// Launch
// ============================================================================
extern "C" void kernel_launch(void* const* d_in, const int* in_sizes, int n_in,
                              void* d_out, int out_size) {
    const float* A = (const float*)d_in[0];   // [8192, 64]
    const float* W = (const float*)d_in[1];   // [5494, 64]
    const float* b = (const float*)d_in[2];   // [5494]
    float* out = (float*)d_out;               // [8192, 82, 67, 1] contiguous

    cudaFuncSetAttribute(gemm_kernel,
                         cudaFuncAttributeMaxDynamicSharedMemorySize, SMEM_BYTES);

    int prep_elems = BATCH * FDIM + PPAD * FDIM;
    prep_kernel<<<(prep_elems + 255) / 256, 256>>>(A, W, b);

    dim3 grid(PPAD / TILE_N, BATCH / (MTILE * MSTEPS));   // 43 x 16
    gemm_kernel<<<grid, 256, SMEM_BYTES>>>(out);
}

// round 7
// speedup vs baseline: 1.3038x; 1.1171x over previous
#include <cuda_runtime.h>
#include <cuda_bf16.h>
#include <cstdint>

// ============================================================================
// Problem constants
// ============================================================================
#define BATCH   8192
#define FDIM    64
#define NXC     82
#define NYC     67
#define PDIM    5494          // NXC*NYC
#define PPAD    5504          // 43 * 128, zero-padded
#define K2      128           // [Ah|Al] and [Wh|Wl]; 3 passes via fragment reuse
#define TILE_N  128
#define MTILE   64            // rows per m-step
#define MSTEPS  4             // m-steps per CTA (grid.y=32 -> 32*4*64 = 8192)
#define PITCH   272           // smem row pitch bytes (256B data + 16B pad)

// ============================================================================
// Scratch (device globals; no allocation allowed)
// ============================================================================
__device__ __align__(16) __nv_bfloat16 g_Acat[BATCH * K2];   // [Ah|Al]
__device__ __align__(16) __nv_bfloat16 g_Wcat[PPAD * K2];    // [Wh|Wl] (permuted rows)
__device__ __align__(16) float         g_bias[PPAD];

// ============================================================================
// Fused prep: bf16 hi/lo split + W row permutation (transpose fold) + bias
// ============================================================================
__global__ void prep_kernel(const float* __restrict__ A,
                            const float* __restrict__ W,
                            const float* __restrict__ b) {
    int e = blockIdx.x * blockDim.x + threadIdx.x;
    if (e < BATCH * FDIM) {
        int m = e >> 6, f = e & 63;
        float v = A[e];
        __nv_bfloat16 h = __float2bfloat16(v);
        __nv_bfloat16 l = __float2bfloat16(v - __bfloat162float(h));
        __nv_bfloat16* row = g_Acat + (size_t)m * K2;
        row[f]      = h;
        row[64 + f] = l;
    } else {
        int e2 = e - BATCH * FDIM;
        if (e2 < PPAD * FDIM) {
            int q = e2 >> 6, f = e2 & 63;   // q = x*67 + y
            float v = 0.0f;
            if (q < PDIM) {
                int x = q / NYC, y = q % NYC;
                v = W[(y * NXC + x) * FDIM + f];
            }
            __nv_bfloat16 h = __float2bfloat16(v);
            __nv_bfloat16 l = __float2bfloat16(v - __bfloat162float(h));
            __nv_bfloat16* row = g_Wcat + (size_t)q * K2;
            row[f]      = h;
            row[64 + f] = l;
            if (f == 0) {
                float bv = 0.0f;
                if (q < PDIM) {
                    int x = q / NYC, y = q % NYC;
                    bv = b[y * NXC + x];
                }
                g_bias[q] = bv;
            }
        }
    }
}

// ============================================================================
// Helpers
// ============================================================================
__device__ __forceinline__ uint32_t smem_u32(const void* p) {
    uint32_t a;
    asm("{ .reg .u64 t; cvta.to.shared.u64 t, %1; cvt.u32.u64 %0, t; }"
        : "=r"(a) : "l"(p));
    return a;
}

__device__ __forceinline__ void cpasync16(uint32_t dst, const void* src) {
    asm volatile("cp.async.cg.shared.global [%0], [%1], 16;"
                 :: "r"(dst), "l"(src));
}
#define CP_COMMIT() asm volatile("cp.async.commit_group;" ::: "memory")
#define CP_WAIT(n)  asm volatile("cp.async.wait_group %0;" :: "n"(n) : "memory")

__device__ __forceinline__ void ldm_x4(uint32_t& r0, uint32_t& r1,
                                       uint32_t& r2, uint32_t& r3, uint32_t addr) {
    asm volatile("ldmatrix.sync.aligned.m8n8.x4.shared.b16 {%0,%1,%2,%3}, [%4];"
                 : "=r"(r0), "=r"(r1), "=r"(r2), "=r"(r3) : "r"(addr));
}

__device__ __forceinline__ void mma16816(float* c, const uint32_t* a,
                                         uint32_t b0, uint32_t b1) {
    asm volatile(
        "mma.sync.aligned.m16n8k16.row.col.f32.bf16.bf16.f32 "
        "{%0,%1,%2,%3}, {%4,%5,%6,%7}, {%8,%9}, {%0,%1,%2,%3};"
        : "+f"(c[0]), "+f"(c[1]), "+f"(c[2]), "+f"(c[3])
        : "r"(a[0]), "r"(a[1]), "r"(a[2]), "r"(a[3]), "r"(b0), "r"(b1));
}

// ============================================================================
// GEMM: persistent W tile, 2-stage cp.async A pipeline over 4 m-tiles of 64.
// CTA tile 64x128 per m-step, 8 warps (2 M x 4 N), warp 32x32.
// 3-pass split-bf16 via fragment reuse: aH*bH + aH*bL + aL*bH per k-step.
// ============================================================================
#define SM_W     0                           // 128*272 = 34816
#define SM_BIAS  34816                       // 512 B
#define SM_A0    35328                       // 64*272 = 17408
#define SM_A1    52736
#define SMEM_BYTES 70144

__global__ void __launch_bounds__(256, 3) gemm_kernel(float* __restrict__ out) {
    extern __shared__ char smem[];
    uint32_t sb = smem_u32(smem);
    int tid  = threadIdx.x;
    int lane = tid & 31;
    int wid  = tid >> 5;
    int wm   = wid & 1;        // warp row (0..1) -> 32 rows each
    int wn   = wid >> 1;       // warp col (0..3) -> 32 cols each
    int n0    = blockIdx.x * TILE_N;
    int mbase = blockIdx.y * MSTEPS;   // first m-tile index

    // ---- stage W tile (persistent, [Wh|Wl] 256B/row) + bias, group 0 ----
    {
        const char* gW = (const char*)(g_Wcat + (size_t)n0 * K2);
        #pragma unroll
        for (int i = tid; i < TILE_N * 16; i += 256) {
            int r = i >> 4, ch = i & 15;
            cpasync16(sb + SM_W + r * PITCH + ch * 16, gW + r * 256 + ch * 16);
        }
        if (tid < TILE_N)
            ((float*)(smem + SM_BIAS))[tid] = g_bias[n0 + tid];
    }
    CP_COMMIT();

    // ---- prologue: A tile 0, group 1 ----
    {
        const char* gA = (const char*)(g_Acat + (size_t)mbase * MTILE * K2);
        #pragma unroll
        for (int i = tid; i < MTILE * 16; i += 256) {
            int r = i >> 4, ch = i & 15;
            cpasync16(sb + SM_A0 + r * PITCH + ch * 16, gA + r * 256 + ch * 16);
        }
    }
    CP_COMMIT();

    // ---- per-lane ldmatrix base addresses ----
    uint32_t aOff = (uint32_t)(wm * 32 + (lane & 15)) * PITCH + ((lane >> 4) * 16);
    uint32_t bBase = sb + SM_W
        + (uint32_t)(wn * 32 + ((lane >> 4) << 3) + (lane & 7)) * PITCH
        + (((lane >> 3) & 1) * 16);
    const float* sbias = (const float*)(smem + SM_BIAS);
    int g = lane >> 2, t = lane & 3;

    #pragma unroll 1
    for (int mt = 0; mt < MSTEPS; mt++) {
        uint32_t bufoff = (mt & 1) ? SM_A1 : SM_A0;

        // prefetch next A tile into the other buffer, then drain current stage
        if (mt < MSTEPS - 1) {
            uint32_t nbuf = (mt & 1) ? SM_A0 : SM_A1;
            const char* gA =
                (const char*)(g_Acat + (size_t)(mbase + mt + 1) * MTILE * K2);
            #pragma unroll
            for (int i = tid; i < MTILE * 16; i += 256) {
                int r = i >> 4, ch = i & 15;
                cpasync16(sb + nbuf + r * PITCH + ch * 16, gA + r * 256 + ch * 16);
            }
            CP_COMMIT();
            CP_WAIT(1);          // current stage (and W) complete
        } else {
            CP_WAIT(0);
        }
        __syncthreads();

        // ---- compute 64x128 from smem ----
        float c[2][4][4];
        #pragma unroll
        for (int mi = 0; mi < 2; mi++)
            #pragma unroll
            for (int ni = 0; ni < 4; ni++)
                #pragma unroll
                for (int r = 0; r < 4; r++) c[mi][ni][r] = 0.0f;

        uint32_t aBase = sb + bufoff + aOff;
        #pragma unroll
        for (int kk = 0; kk < 4; kk++) {     // 4 k-steps of 16 over the 64 features
            uint32_t aH[2][4], aL[2][4];
            #pragma unroll
            for (int mi = 0; mi < 2; mi++) {
                ldm_x4(aH[mi][0], aH[mi][1], aH[mi][2], aH[mi][3],
                       aBase + mi * 16 * PITCH + kk * 32);
                ldm_x4(aL[mi][0], aL[mi][1], aL[mi][2], aL[mi][3],
                       aBase + mi * 16 * PITCH + 128 + kk * 32);
            }
            uint32_t bH[2][4], bL[2][4];
            #pragma unroll
            for (int nq = 0; nq < 2; nq++) {
                ldm_x4(bH[nq][0], bH[nq][1], bH[nq][2], bH[nq][3],
                       bBase + nq * 16 * PITCH + kk * 32);
                ldm_x4(bL[nq][0], bL[nq][1], bL[nq][2], bL[nq][3],
                       bBase + nq * 16 * PITCH + 128 + kk * 32);
            }
            #pragma unroll
            for (int mi = 0; mi < 2; mi++)
                #pragma unroll
                for (int ni = 0; ni < 4; ni++) {
                    int nq = ni >> 1, h = (ni & 1) * 2;
                    mma16816(c[mi][ni], aH[mi], bH[nq][h], bH[nq][h + 1]); // Ah*Wh
                    mma16816(c[mi][ni], aH[mi], bL[nq][h], bL[nq][h + 1]); // Ah*Wl
                    mma16816(c[mi][ni], aL[mi], bH[nq][h], bH[nq][h + 1]); // Al*Wh
                }
        }

        // ---- epilogue: +bias, direct float2 stores ----
        int m0 = (mbase + mt) * MTILE;
        #pragma unroll
        for (int mi = 0; mi < 2; mi++) {
            int r0 = m0 + wm * 32 + mi * 16 + g;    // and r0+8
            #pragma unroll
            for (int ni = 0; ni < 4; ni++) {
                int lc = wn * 32 + ni * 8 + 2 * t;  // local col (even)
                int n  = n0 + lc;
                if (n < PDIM) {                      // PDIM even -> pair safe
                    float b0 = sbias[lc], b1 = sbias[lc + 1];
                    float2 v0 = {c[mi][ni][0] + b0, c[mi][ni][1] + b1};
                    float2 v1 = {c[mi][ni][2] + b0, c[mi][ni][3] + b1};
                    *(float2*)(out + (size_t)r0 * PDIM + n) = v0;
                    *(float2*)(out + (size_t)(r0 + 8) * PDIM + n) = v1;
                }
            }
        }
        __syncthreads();   // all warps done reading bufoff before refill
    }
}

// ============================================================================
// Launch
// ============================================================================
extern "C" void kernel_launch(void* const* d_in, const int* in_sizes, int n_in,
                              void* d_out, int out_size) {
    const float* A = (const float*)d_in[0];   // [8192, 64]
    const float* W = (const float*)d_in[1];   // [5494, 64]
    const float* b = (const float*)d_in[2];   // [5494]
    float* out = (float*)d_out;               // [8192, 82, 67, 1] contiguous

    cudaFuncSetAttribute(gemm_kernel,
                         cudaFuncAttributeMaxDynamicSharedMemorySize, SMEM_BYTES);

    int prep_elems = BATCH * FDIM + PPAD * FDIM;
    prep_kernel<<<(prep_elems + 255) / 256, 256>>>(A, W, b);

    dim3 grid(PPAD / TILE_N, BATCH / (MTILE * MSTEPS));   // 43 x 32
    gemm_kernel<<<grid, 256, SMEM_BYTES>>>(out);
}

// round 10
// speedup vs baseline: 1.3114x; 1.0058x over previous
#include <cuda_runtime.h>
#include <cuda_bf16.h>
#include <cstdint>

// ============================================================================
// Problem constants
// ============================================================================
#define BATCH   8192
#define FDIM    64
#define NXC     82
#define NYC     67
#define PDIM    5494          // NXC*NYC
#define PPAD    5504          // 43 * 128, zero-padded
#define K2      128           // [Ah|Al] and [Wh|Wl]; 3 passes via fragment reuse
#define TILE_N  128
#define MTILE   64            // rows per m-step
#define MSTEPS  4             // m-steps per CTA (grid.y=32 -> 32*4*64 = 8192)
#define PITCH   272           // smem row pitch bytes (256B data + 16B pad)

// ============================================================================
// Scratch (device globals; no allocation allowed)
// ============================================================================
__device__ __align__(16) __nv_bfloat16 g_Acat[BATCH * K2];   // [Ah|Al]
__device__ __align__(16) __nv_bfloat16 g_Wcat[PPAD * K2];    // [Wh|Wl] (permuted rows)
__device__ __align__(16) float         g_bias[PPAD];

// ============================================================================
// Fused prep: bf16 hi/lo split + W row permutation (transpose fold) + bias
// ============================================================================
__global__ void prep_kernel(const float* __restrict__ A,
                            const float* __restrict__ W,
                            const float* __restrict__ b) {
    int e = blockIdx.x * blockDim.x + threadIdx.x;
    if (e < BATCH * FDIM) {
        int m = e >> 6, f = e & 63;
        float v = A[e];
        __nv_bfloat16 h = __float2bfloat16(v);
        __nv_bfloat16 l = __float2bfloat16(v - __bfloat162float(h));
        __nv_bfloat16* row = g_Acat + (size_t)m * K2;
        row[f]      = h;
        row[64 + f] = l;
    } else {
        int e2 = e - BATCH * FDIM;
        if (e2 < PPAD * FDIM) {
            int q = e2 >> 6, f = e2 & 63;   // q = x*67 + y
            float v = 0.0f;
            if (q < PDIM) {
                int x = q / NYC, y = q % NYC;
                v = W[(y * NXC + x) * FDIM + f];
            }
            __nv_bfloat16 h = __float2bfloat16(v);
            __nv_bfloat16 l = __float2bfloat16(v - __bfloat162float(h));
            __nv_bfloat16* row = g_Wcat + (size_t)q * K2;
            row[f]      = h;
            row[64 + f] = l;
            if (f == 0) {
                float bv = 0.0f;
                if (q < PDIM) {
                    int x = q / NYC, y = q % NYC;
                    bv = b[y * NXC + x];
                }
                g_bias[q] = bv;
            }
        }
    }
}

// ============================================================================
// Helpers
// ============================================================================
__device__ __forceinline__ uint32_t smem_u32(const void* p) {
    uint32_t a;
    asm("{ .reg .u64 t; cvta.to.shared.u64 t, %1; cvt.u32.u64 %0, t; }"
        : "=r"(a) : "l"(p));
    return a;
}

__device__ __forceinline__ void cpasync16(uint32_t dst, const void* src) {
    asm volatile("cp.async.cg.shared.global [%0], [%1], 16;"
                 :: "r"(dst), "l"(src));
}
#define CP_COMMIT() asm volatile("cp.async.commit_group;" ::: "memory")
#define CP_WAIT(n)  asm volatile("cp.async.wait_group %0;" :: "n"(n) : "memory")

__device__ __forceinline__ void ldm_x4(uint32_t& r0, uint32_t& r1,
                                       uint32_t& r2, uint32_t& r3, uint32_t addr) {
    asm volatile("ldmatrix.sync.aligned.m8n8.x4.shared.b16 {%0,%1,%2,%3}, [%4];"
                 : "=r"(r0), "=r"(r1), "=r"(r2), "=r"(r3) : "r"(addr));
}

__device__ __forceinline__ void mma16816(float* c, const uint32_t* a,
                                         uint32_t b0, uint32_t b1) {
    asm volatile(
        "mma.sync.aligned.m16n8k16.row.col.f32.bf16.bf16.f32 "
        "{%0,%1,%2,%3}, {%4,%5,%6,%7}, {%8,%9}, {%0,%1,%2,%3};"
        : "+f"(c[0]), "+f"(c[1]), "+f"(c[2]), "+f"(c[3])
        : "r"(a[0]), "r"(a[1]), "r"(a[2]), "r"(a[3]), "r"(b0), "r"(b1));
}

// ============================================================================
// GEMM: W FRAGMENTS PERSISTENT IN REGISTERS (loaded once per CTA), A streamed
// through a 2-stage cp.async ping-pong over 4 m-tiles of 64.
// CTA tile 64x128 per m-step, 8 warps (2 M x 4 N), warp 32x32.
// 3-pass split-bf16 via fragment reuse: aH*bH + aH*bL + aL*bH per k-step.
// Mainloop per k-step: 4 ldmatrix (A only) + 24 MMA  (ratio 6).
// ============================================================================
#define SM_W     0                           // 128*272 = 34816 (read only once)
#define SM_BIAS  34816                       // 512 B
#define SM_A0    35328                       // 64*272 = 17408
#define SM_A1    52736
#define SMEM_BYTES 70144

__global__ void __launch_bounds__(256, 2) gemm_kernel(float* __restrict__ out) {
    extern __shared__ char smem[];
    uint32_t sb = smem_u32(smem);
    int tid  = threadIdx.x;
    int lane = tid & 31;
    int wid  = tid >> 5;
    int wm   = wid & 1;        // warp row (0..1) -> 32 rows each
    int wn   = wid >> 1;       // warp col (0..3) -> 32 cols each
    int n0    = blockIdx.x * TILE_N;
    int mbase = blockIdx.y * MSTEPS;   // first m-tile index

    // ---- stage W tile ([Wh|Wl] 256B/row) + bias, group 0 ----
    {
        const char* gW = (const char*)(g_Wcat + (size_t)n0 * K2);
        #pragma unroll
        for (int i = tid; i < TILE_N * 16; i += 256) {
            int r = i >> 4, ch = i & 15;
            cpasync16(sb + SM_W + r * PITCH + ch * 16, gW + r * 256 + ch * 16);
        }
        if (tid < TILE_N)
            ((float*)(smem + SM_BIAS))[tid] = g_bias[n0 + tid];
    }
    CP_COMMIT();

    // ---- prologue: A tile 0, group 1 ----
    {
        const char* gA = (const char*)(g_Acat + (size_t)mbase * MTILE * K2);
        #pragma unroll
        for (int i = tid; i < MTILE * 16; i += 256) {
            int r = i >> 4, ch = i & 15;
            cpasync16(sb + SM_A0 + r * PITCH + ch * 16, gA + r * 256 + ch * 16);
        }
    }
    CP_COMMIT();

    // ---- per-lane ldmatrix base addresses ----
    uint32_t aOff = (uint32_t)(wm * 32 + (lane & 15)) * PITCH + ((lane >> 4) * 16);
    uint32_t bBase = sb + SM_W
        + (uint32_t)(wn * 32 + ((lane >> 4) << 3) + (lane & 7)) * PITCH
        + (((lane >> 3) & 1) * 16);
    const float* sbias = (const float*)(smem + SM_BIAS);
    int g = lane >> 2, t = lane & 3;

    // ---- load ALL W fragments into registers: [kk][nq][H/L][4] = 64 regs ----
    CP_WAIT(1);              // W staged (A0 may still be in flight)
    __syncthreads();
    uint32_t bF[4][2][2][4];
    #pragma unroll
    for (int kk = 0; kk < 4; kk++)
        #pragma unroll
        for (int nq = 0; nq < 2; nq++) {
            ldm_x4(bF[kk][nq][0][0], bF[kk][nq][0][1],
                   bF[kk][nq][0][2], bF[kk][nq][0][3],
                   bBase + nq * 16 * PITCH + kk * 32);         // Wh
            ldm_x4(bF[kk][nq][1][0], bF[kk][nq][1][1],
                   bF[kk][nq][1][2], bF[kk][nq][1][3],
                   bBase + nq * 16 * PITCH + 128 + kk * 32);   // Wl
        }
    // W smem region is never overwritten -> no barrier needed after this.

    #pragma unroll 1
    for (int mt = 0; mt < MSTEPS; mt++) {
        uint32_t bufoff = (mt & 1) ? SM_A1 : SM_A0;

        // prefetch next A tile into the other buffer, then drain current stage
        if (mt < MSTEPS - 1) {
            uint32_t nbuf = (mt & 1) ? SM_A0 : SM_A1;
            const char* gA =
                (const char*)(g_Acat + (size_t)(mbase + mt + 1) * MTILE * K2);
            #pragma unroll
            for (int i = tid; i < MTILE * 16; i += 256) {
                int r = i >> 4, ch = i & 15;
                cpasync16(sb + nbuf + r * PITCH + ch * 16, gA + r * 256 + ch * 16);
            }
            CP_COMMIT();
            CP_WAIT(1);          // current A stage complete
        } else {
            CP_WAIT(0);
        }
        __syncthreads();

        // ---- compute 64x128 from smem A + register-resident W ----
        float c[2][4][4];
        #pragma unroll
        for (int mi = 0; mi < 2; mi++)
            #pragma unroll
            for (int ni = 0; ni < 4; ni++)
                #pragma unroll
                for (int r = 0; r < 4; r++) c[mi][ni][r] = 0.0f;

        uint32_t aBase = sb + bufoff + aOff;
        #pragma unroll
        for (int kk = 0; kk < 4; kk++) {     // 4 k-steps of 16 over 64 features
            uint32_t aH[2][4], aL[2][4];
            #pragma unroll
            for (int mi = 0; mi < 2; mi++) {
                ldm_x4(aH[mi][0], aH[mi][1], aH[mi][2], aH[mi][3],
                       aBase + mi * 16 * PITCH + kk * 32);
                ldm_x4(aL[mi][0], aL[mi][1], aL[mi][2], aL[mi][3],
                       aBase + mi * 16 * PITCH + 128 + kk * 32);
            }
            #pragma unroll
            for (int mi = 0; mi < 2; mi++)
                #pragma unroll
                for (int ni = 0; ni < 4; ni++) {
                    int nq = ni >> 1, h = (ni & 1) * 2;
                    mma16816(c[mi][ni], aH[mi],
                             bF[kk][nq][0][h], bF[kk][nq][0][h + 1]); // Ah*Wh
                    mma16816(c[mi][ni], aH[mi],
                             bF[kk][nq][1][h], bF[kk][nq][1][h + 1]); // Ah*Wl
                    mma16816(c[mi][ni], aL[mi],
                             bF[kk][nq][0][h], bF[kk][nq][0][h + 1]); // Al*Wh
                }
        }

        // ---- epilogue: +bias, direct float2 stores ----
        int m0 = (mbase + mt) * MTILE;
        #pragma unroll
        for (int mi = 0; mi < 2; mi++) {
            int r0 = m0 + wm * 32 + mi * 16 + g;    // and r0+8
            #pragma unroll
            for (int ni = 0; ni < 4; ni++) {
                int lc = wn * 32 + ni * 8 + 2 * t;  // local col (even)
                int n  = n0 + lc;
                if (n < PDIM) {                      // PDIM even -> pair safe
                    float b0 = sbias[lc], b1 = sbias[lc + 1];
                    float2 v0 = {c[mi][ni][0] + b0, c[mi][ni][1] + b1};
                    float2 v1 = {c[mi][ni][2] + b0, c[mi][ni][3] + b1};
                    *(float2*)(out + (size_t)r0 * PDIM + n) = v0;
                    *(float2*)(out + (size_t)(r0 + 8) * PDIM + n) = v1;
                }
            }
        }
        __syncthreads();   // all warps done reading bufoff before refill
    }
}

// ============================================================================
// Launch
// ============================================================================
extern "C" void kernel_launch(void* const* d_in, const int* in_sizes, int n_in,
                              void* d_out, int out_size) {
    const float* A = (const float*)d_in[0];   // [8192, 64]
    const float* W = (const float*)d_in[1];   // [5494, 64]
    const float* b = (const float*)d_in[2];   // [5494]
    float* out = (float*)d_out;               // [8192, 82, 67, 1] contiguous

    cudaFuncSetAttribute(gemm_kernel,
                         cudaFuncAttributeMaxDynamicSharedMemorySize, SMEM_BYTES);

    int prep_elems = BATCH * FDIM + PPAD * FDIM;
    prep_kernel<<<(prep_elems + 255) / 256, 256>>>(A, W, b);

    dim3 grid(PPAD / TILE_N, BATCH / (MTILE * MSTEPS));   // 43 x 32
    gemm_kernel<<<grid, 256, SMEM_BYTES>>>(out);
}

// round 11
// speedup vs baseline: 1.5687x; 1.1962x over previous
#include <cuda_runtime.h>
#include <cuda_fp16.h>
#include <cstdint>

// ============================================================================
// Problem constants
// ============================================================================
#define BATCH   8192
#define FDIM    64
#define NXC     82
#define NYC     67
#define PDIM    5494          // NXC*NYC
#define PPAD    5504          // 43 * 128, zero-padded
#define TILE_N  128
#define MTILE   64            // rows per m-step
#define MSTEPS  4             // m-steps per CTA: CTA covers 256 batch rows
#define PITCH   144           // smem row pitch bytes (128B data + 16B pad)

// ============================================================================
// Scratch (device globals; no allocation allowed)
// ============================================================================
__device__ __align__(16) __half g_Ah[BATCH * FDIM];   // fp16 inputs
__device__ __align__(16) __half g_Wh[PPAD * FDIM];    // fp16 W, rows permuted
__device__ __align__(16) float  g_bias[PPAD];

// ============================================================================
// Fused prep: fp16 convert + W row permutation (transpose fold) + bias
// ============================================================================
__global__ void prep_kernel(const float* __restrict__ A,
                            const float* __restrict__ W,
                            const float* __restrict__ b) {
    int e = blockIdx.x * blockDim.x + threadIdx.x;
    if (e < BATCH * FDIM) {
        g_Ah[e] = __float2half(A[e]);
    } else {
        int e2 = e - BATCH * FDIM;
        if (e2 < PPAD * FDIM) {
            int q = e2 >> 6, f = e2 & 63;   // q = x*67 + y
            float v = 0.0f;
            if (q < PDIM) {
                int x = q / NYC, y = q % NYC;
                v = W[(y * NXC + x) * FDIM + f];
            }
            g_Wh[e2] = __float2half(v);
            if (f == 0) {
                float bv = 0.0f;
                if (q < PDIM) {
                    int x = q / NYC, y = q % NYC;
                    bv = b[y * NXC + x];
                }
                g_bias[q] = bv;
            }
        }
    }
}

// ============================================================================
// Helpers
// ============================================================================
__device__ __forceinline__ uint32_t smem_u32(const void* p) {
    uint32_t a;
    asm("{ .reg .u64 t; cvta.to.shared.u64 t, %1; cvt.u32.u64 %0, t; }"
        : "=r"(a) : "l"(p));
    return a;
}

__device__ __forceinline__ void cpasync16(uint32_t dst, const void* src) {
    asm volatile("cp.async.cg.shared.global [%0], [%1], 16;"
                 :: "r"(dst), "l"(src));
}
#define CP_COMMIT() asm volatile("cp.async.commit_group;" ::: "memory")
#define CP_WAIT(n)  asm volatile("cp.async.wait_group %0;" :: "n"(n) : "memory")

__device__ __forceinline__ void ldm_x4(uint32_t& r0, uint32_t& r1,
                                       uint32_t& r2, uint32_t& r3, uint32_t addr) {
    asm volatile("ldmatrix.sync.aligned.m8n8.x4.shared.b16 {%0,%1,%2,%3}, [%4];"
                 : "=r"(r0), "=r"(r1), "=r"(r2), "=r"(r3) : "r"(addr));
}

__device__ __forceinline__ void mma16816(float* c, const uint32_t* a,
                                         uint32_t b0, uint32_t b1) {
    asm volatile(
        "mma.sync.aligned.m16n8k16.row.col.f32.f16.f16.f32 "
        "{%0,%1,%2,%3}, {%4,%5,%6,%7}, {%8,%9}, {%0,%1,%2,%3};"
        : "+f"(c[0]), "+f"(c[1]), "+f"(c[2]), "+f"(c[3])
        : "r"(a[0]), "r"(a[1]), "r"(a[2]), "r"(a[3]), "r"(b0), "r"(b1));
}

// ============================================================================
// GEMM: single-pass fp16, whole CTA working set staged ONCE (one barrier),
// W fragments register-resident, 4 barrier-free m-steps of 64 rows.
// CTA tile 64x128 per m-step, 8 warps (2 M x 4 N), warp 32x32.
// Mainloop per m-step per warp: 8 ldmatrix + 32 MMA + 16 STG.64.
// ============================================================================
#define SM_A     0                            // 256*144 = 36864
#define SM_W     36864                        // 128*144 = 18432
#define SM_BIAS  55296                        // 512
#define SMEM_BYTES 55808

__global__ void __launch_bounds__(256, 2) gemm_kernel(float* __restrict__ out) {
    extern __shared__ char smem[];
    uint32_t sb = smem_u32(smem);
    int tid  = threadIdx.x;
    int lane = tid & 31;
    int wid  = tid >> 5;
    int wm   = wid & 1;        // warp row (0..1) -> 32 rows each
    int wn   = wid >> 1;       // warp col (0..3) -> 32 cols each
    int n0 = blockIdx.x * TILE_N;
    int m0 = blockIdx.y * (MTILE * MSTEPS);   // 256 rows per CTA

    // ---- stage ALL A rows (256x128B) + W tile (128x128B) + bias, once ----
    {
        const char* gA = (const char*)(g_Ah + (size_t)m0 * FDIM);
        #pragma unroll
        for (int i = tid; i < 256 * 8; i += 256) {
            int r = i >> 3, ch = i & 7;
            cpasync16(sb + SM_A + r * PITCH + ch * 16, gA + r * 128 + ch * 16);
        }
        const char* gW = (const char*)(g_Wh + (size_t)n0 * FDIM);
        #pragma unroll
        for (int i = tid; i < 128 * 8; i += 256) {
            int r = i >> 3, ch = i & 7;
            cpasync16(sb + SM_W + r * PITCH + ch * 16, gW + r * 128 + ch * 16);
        }
        if (tid < TILE_N)
            ((float*)(smem + SM_BIAS))[tid] = g_bias[n0 + tid];
    }
    CP_COMMIT();
    CP_WAIT(0);
    __syncthreads();            // the ONLY barrier in this kernel

    // ---- W fragments -> registers: [kk][nq][4] = 32 regs ----
    uint32_t bBase = sb + SM_W
        + (uint32_t)(wn * 32 + ((lane >> 4) << 3) + (lane & 7)) * PITCH
        + (((lane >> 3) & 1) * 16);
    uint32_t bF[4][2][4];
    #pragma unroll
    for (int kk = 0; kk < 4; kk++)
        #pragma unroll
        for (int nq = 0; nq < 2; nq++)
            ldm_x4(bF[kk][nq][0], bF[kk][nq][1], bF[kk][nq][2], bF[kk][nq][3],
                   bBase + nq * 16 * PITCH + kk * 32);

    uint32_t aOff = sb + SM_A
        + (uint32_t)(wm * 32 + (lane & 15)) * PITCH + ((lane >> 4) * 16);
    const float* sbias = (const float*)(smem + SM_BIAS);
    int g = lane >> 2, t = lane & 3;

    #pragma unroll 1
    for (int mt = 0; mt < MSTEPS; mt++) {
        float c[2][4][4];
        #pragma unroll
        for (int mi = 0; mi < 2; mi++)
            #pragma unroll
            for (int ni = 0; ni < 4; ni++)
                #pragma unroll
                for (int r = 0; r < 4; r++) c[mi][ni][r] = 0.0f;

        uint32_t aBase = aOff + (uint32_t)(mt * MTILE) * PITCH;
        #pragma unroll
        for (int kk = 0; kk < 4; kk++) {     // K=64: 4 k-steps of 16
            uint32_t aF[2][4];
            #pragma unroll
            for (int mi = 0; mi < 2; mi++)
                ldm_x4(aF[mi][0], aF[mi][1], aF[mi][2], aF[mi][3],
                       aBase + mi * 16 * PITCH + kk * 32);
            #pragma unroll
            for (int mi = 0; mi < 2; mi++)
                #pragma unroll
                for (int ni = 0; ni < 4; ni++)
                    mma16816(c[mi][ni], aF[mi],
                             bF[kk][ni >> 1][(ni & 1) * 2],
                             bF[kk][ni >> 1][(ni & 1) * 2 + 1]);
        }

        // ---- epilogue: +bias, direct float2 stores ----
        int mrow = m0 + mt * MTILE;
        #pragma unroll
        for (int mi = 0; mi < 2; mi++) {
            int r0 = mrow + wm * 32 + mi * 16 + g;   // and r0+8
            #pragma unroll
            for (int ni = 0; ni < 4; ni++) {
                int lc = wn * 32 + ni * 8 + 2 * t;   // local col (even)
                int n  = n0 + lc;
                if (n < PDIM) {                       // PDIM even -> pair safe
                    float b0 = sbias[lc], b1 = sbias[lc + 1];
                    float2 v0 = {c[mi][ni][0] + b0, c[mi][ni][1] + b1};
                    float2 v1 = {c[mi][ni][2] + b0, c[mi][ni][3] + b1};
                    *(float2*)(out + (size_t)r0 * PDIM + n) = v0;
                    *(float2*)(out + (size_t)(r0 + 8) * PDIM + n) = v1;
                }
            }
        }
        // no barrier: smem is read-only after the single staging sync
    }
}

// ============================================================================
// Launch
// ============================================================================
extern "C" void kernel_launch(void* const* d_in, const int* in_sizes, int n_in,
                              void* d_out, int out_size) {
    const float* A = (const float*)d_in[0];   // [8192, 64]
    const float* W = (const float*)d_in[1];   // [5494, 64]
    const float* b = (const float*)d_in[2];   // [5494]
    float* out = (float*)d_out;               // [8192, 82, 67, 1] contiguous

    cudaFuncSetAttribute(gemm_kernel,
                         cudaFuncAttributeMaxDynamicSharedMemorySize, SMEM_BYTES);

    int prep_elems = BATCH * FDIM + PPAD * FDIM;
    prep_kernel<<<(prep_elems + 255) / 256, 256>>>(A, W, b);

    dim3 grid(PPAD / TILE_N, BATCH / (MTILE * MSTEPS));   // 43 x 32
    gemm_kernel<<<grid, 256, SMEM_BYTES>>>(out);
}

// round 12
// speedup vs baseline: 1.8062x; 1.1514x over previous
#include <cuda_runtime.h>
#include <cuda_fp16.h>
#include <cstdint>

// ============================================================================
// Problem constants
// ============================================================================
#define BATCH   8192
#define FDIM    64
#define NXC     82
#define NYC     67
#define PDIM    5494          // NXC*NYC
#define PPAD    5504          // 43 * 128, zero-padded
#define TILE_N  128
#define MTILE   64            // rows per m-step
#define MSTEPS  4             // m-steps per CTA: CTA covers 256 batch rows
#define PITCH   144           // smem operand row pitch bytes (128B data + 16B pad)
#define OPITCHF 132           // output staging pitch in floats (128 + 4)

// ============================================================================
// Scratch (device globals; no allocation allowed)
// ============================================================================
__device__ __align__(16) __half g_Ah[BATCH * FDIM];   // fp16 inputs
__device__ __align__(16) __half g_Wh[PPAD * FDIM];    // fp16 W, rows permuted
__device__ __align__(16) float  g_bias[PPAD];

// ============================================================================
// Fused prep: fp16 convert + W row permutation (transpose fold) + bias
// ============================================================================
__global__ void prep_kernel(const float* __restrict__ A,
                            const float* __restrict__ W,
                            const float* __restrict__ b) {
    int e = blockIdx.x * blockDim.x + threadIdx.x;
    if (e < BATCH * FDIM) {
        g_Ah[e] = __float2half(A[e]);
    } else {
        int e2 = e - BATCH * FDIM;
        if (e2 < PPAD * FDIM) {
            int q = e2 >> 6, f = e2 & 63;   // q = x*67 + y
            float v = 0.0f;
            if (q < PDIM) {
                int x = q / NYC, y = q % NYC;
                v = W[(y * NXC + x) * FDIM + f];
            }
            g_Wh[e2] = __float2half(v);
            if (f == 0) {
                float bv = 0.0f;
                if (q < PDIM) {
                    int x = q / NYC, y = q % NYC;
                    bv = b[y * NXC + x];
                }
                g_bias[q] = bv;
            }
        }
    }
}

// ============================================================================
// Helpers
// ============================================================================
__device__ __forceinline__ uint32_t smem_u32(const void* p) {
    uint32_t a;
    asm("{ .reg .u64 t; cvta.to.shared.u64 t, %1; cvt.u32.u64 %0, t; }"
        : "=r"(a) : "l"(p));
    return a;
}

__device__ __forceinline__ void cpasync16(uint32_t dst, const void* src) {
    asm volatile("cp.async.cg.shared.global [%0], [%1], 16;"
                 :: "r"(dst), "l"(src));
}
#define CP_COMMIT() asm volatile("cp.async.commit_group;" ::: "memory")
#define CP_WAIT(n)  asm volatile("cp.async.wait_group %0;" :: "n"(n) : "memory")

__device__ __forceinline__ void ldm_x4(uint32_t& r0, uint32_t& r1,
                                       uint32_t& r2, uint32_t& r3, uint32_t addr) {
    asm volatile("ldmatrix.sync.aligned.m8n8.x4.shared.b16 {%0,%1,%2,%3}, [%4];"
                 : "=r"(r0), "=r"(r1), "=r"(r2), "=r"(r3) : "r"(addr));
}

__device__ __forceinline__ void mma16816(float* c, const uint32_t* a,
                                         uint32_t b0, uint32_t b1) {
    asm volatile(
        "mma.sync.aligned.m16n8k16.row.col.f32.f16.f16.f32 "
        "{%0,%1,%2,%3}, {%4,%5,%6,%7}, {%8,%9}, {%0,%1,%2,%3};"
        : "+f"(c[0]), "+f"(c[1]), "+f"(c[2]), "+f"(c[3])
        : "r"(a[0]), "r"(a[1]), "r"(a[2]), "r"(a[3]), "r"(b0), "r"(b1));
}

// ============================================================================
// GEMM: single-pass fp16, whole working set staged once, W frags in registers,
// 4 m-steps of 64 rows with SMEM-TRANSPOSED epilogue: one warp stores one
// contiguous 256B output-row chunk per STG.64 (2 L1 wavefronts vs 8 before).
// ============================================================================
#define SM_A     0                            // 256*144 = 36864
#define SM_W     36864                        // 128*144 = 18432
#define SM_BIAS  55296                        // 512
#define SM_O     55808                        // 64*132*4 = 33792
#define SMEM_BYTES 89600

__global__ void __launch_bounds__(256, 2) gemm_kernel(float* __restrict__ out) {
    extern __shared__ char smem[];
    uint32_t sb = smem_u32(smem);
    int tid  = threadIdx.x;
    int lane = tid & 31;
    int wid  = tid >> 5;
    int wm   = wid & 1;        // warp row (0..1) -> 32 rows each
    int wn   = wid >> 1;       // warp col (0..3) -> 32 cols each
    int n0 = blockIdx.x * TILE_N;
    int m0 = blockIdx.y * (MTILE * MSTEPS);   // 256 rows per CTA

    // ---- stage ALL A rows (256x128B) + W tile (128x128B) + bias, once ----
    {
        const char* gA = (const char*)(g_Ah + (size_t)m0 * FDIM);
        #pragma unroll
        for (int i = tid; i < 256 * 8; i += 256) {
            int r = i >> 3, ch = i & 7;
            cpasync16(sb + SM_A + r * PITCH + ch * 16, gA + r * 128 + ch * 16);
        }
        const char* gW = (const char*)(g_Wh + (size_t)n0 * FDIM);
        #pragma unroll
        for (int i = tid; i < 128 * 8; i += 256) {
            int r = i >> 3, ch = i & 7;
            cpasync16(sb + SM_W + r * PITCH + ch * 16, gW + r * 128 + ch * 16);
        }
        if (tid < TILE_N)
            ((float*)(smem + SM_BIAS))[tid] = g_bias[n0 + tid];
    }
    CP_COMMIT();
    CP_WAIT(0);
    __syncthreads();

    // ---- W fragments -> registers: [kk][nq][4] = 32 regs ----
    uint32_t bBase = sb + SM_W
        + (uint32_t)(wn * 32 + ((lane >> 4) << 3) + (lane & 7)) * PITCH
        + (((lane >> 3) & 1) * 16);
    uint32_t bF[4][2][4];
    #pragma unroll
    for (int kk = 0; kk < 4; kk++)
        #pragma unroll
        for (int nq = 0; nq < 2; nq++)
            ldm_x4(bF[kk][nq][0], bF[kk][nq][1], bF[kk][nq][2], bF[kk][nq][3],
                   bBase + nq * 16 * PITCH + kk * 32);

    uint32_t aOff = sb + SM_A
        + (uint32_t)(wm * 32 + (lane & 15)) * PITCH + ((lane >> 4) * 16);
    int g = lane >> 2, t = lane & 3;

    // per-lane epilogue constants: lane covers cols {2*lane, 2*lane+1} in each
    // 64-col phase of a row (same columns for EVERY row)
    const float* sbias = (const float*)(smem + SM_BIAS);
    float2 bias2[2];
    #pragma unroll
    for (int ph = 0; ph < 2; ph++) {
        bias2[ph].x = sbias[ph * 64 + 2 * lane];
        bias2[ph].y = sbias[ph * 64 + 2 * lane + 1];
    }
    bool pvalid[2];
    #pragma unroll
    for (int ph = 0; ph < 2; ph++)
        pvalid[ph] = (n0 + ph * 64 + 2 * lane) < PDIM;   // PDIM even -> pair safe

    uint32_t oBase = sb + SM_O;
    uint32_t stsR = (uint32_t)(wm * 32 + g);          // + mi*16 (+8)
    uint32_t stsC = (uint32_t)(wn * 32 + 2 * t);      // + ni*8

    #pragma unroll 1
    for (int mt = 0; mt < MSTEPS; mt++) {
        float c[2][4][4];
        #pragma unroll
        for (int mi = 0; mi < 2; mi++)
            #pragma unroll
            for (int ni = 0; ni < 4; ni++)
                #pragma unroll
                for (int r = 0; r < 4; r++) c[mi][ni][r] = 0.0f;

        uint32_t aBase = aOff + (uint32_t)(mt * MTILE) * PITCH;
        #pragma unroll
        for (int kk = 0; kk < 4; kk++) {     // K=64: 4 k-steps of 16
            uint32_t aF[2][4];
            #pragma unroll
            for (int mi = 0; mi < 2; mi++)
                ldm_x4(aF[mi][0], aF[mi][1], aF[mi][2], aF[mi][3],
                       aBase + mi * 16 * PITCH + kk * 32);
            #pragma unroll
            for (int mi = 0; mi < 2; mi++)
                #pragma unroll
                for (int ni = 0; ni < 4; ni++)
                    mma16816(c[mi][ni], aF[mi],
                             bF[kk][ni >> 1][(ni & 1) * 2],
                             bF[kk][ni >> 1][(ni & 1) * 2 + 1]);
        }

        // ---- dump accumulators to staging tile (64 x OPITCHF floats) ----
        #pragma unroll
        for (int mi = 0; mi < 2; mi++)
            #pragma unroll
            for (int ni = 0; ni < 4; ni++) {
                uint32_t r = stsR + mi * 16;
                uint32_t cadr = oBase + ((r * OPITCHF + stsC + ni * 8) << 2);
                asm volatile("st.shared.v2.f32 [%0], {%1, %2};"
                             :: "r"(cadr), "f"(c[mi][ni][0]), "f"(c[mi][ni][1])
                             : "memory");
                asm volatile("st.shared.v2.f32 [%0], {%1, %2};"
                             :: "r"(cadr + ((8u * OPITCHF) << 2)),
                                "f"(c[mi][ni][2]), "f"(c[mi][ni][3])
                             : "memory");
            }
        __syncthreads();

        // ---- contiguous row stores: warp wid handles rows wid*8..wid*8+7 ----
        int mrow = m0 + mt * MTILE;
        #pragma unroll
        for (int r = 0; r < 8; r++) {
            int lr = wid * 8 + r;                      // local row 0..63
            float* orow = out + (size_t)(mrow + lr) * PDIM + n0;
            uint32_t radr = oBase + ((uint32_t)(lr * OPITCHF + 2 * lane) << 2);
            #pragma unroll
            for (int ph = 0; ph < 2; ph++) {
                if (pvalid[ph]) {
                    float2 v;
                    asm volatile("ld.shared.v2.f32 {%0, %1}, [%2];"
                                 : "=f"(v.x), "=f"(v.y)
                                 : "r"(radr + ((ph * 64u) << 2)));
                    v.x += bias2[ph].x;
                    v.y += bias2[ph].y;
                    *(float2*)(orow + ph * 64 + 2 * lane) = v;
                }
            }
        }
        __syncthreads();   // staging tile reusable for next m-step
    }
}

// ============================================================================
// Launch
// ============================================================================
extern "C" void kernel_launch(void* const* d_in, const int* in_sizes, int n_in,
                              void* d_out, int out_size) {
    const float* A = (const float*)d_in[0];   // [8192, 64]
    const float* W = (const float*)d_in[1];   // [5494, 64]
    const float* b = (const float*)d_in[2];   // [5494]
    float* out = (float*)d_out;               // [8192, 82, 67, 1] contiguous

    cudaFuncSetAttribute(gemm_kernel,
                         cudaFuncAttributeMaxDynamicSharedMemorySize, SMEM_BYTES);

    int prep_elems = BATCH * FDIM + PPAD * FDIM;
    prep_kernel<<<(prep_elems + 255) / 256, 256>>>(A, W, b);

    dim3 grid(PPAD / TILE_N, BATCH / (MTILE * MSTEPS));   // 43 x 32
    gemm_kernel<<<grid, 256, SMEM_BYTES>>>(out);
}

// round 13
// speedup vs baseline: 1.8367x; 1.0169x over previous
#include <cuda_runtime.h>
#include <cuda_fp16.h>
#include <cstdint>

// ============================================================================
// Problem constants
// ============================================================================
#define BATCH   8192
#define FDIM    64
#define NXC     82
#define NYC     67
#define PDIM    5494          // NXC*NYC
#define PPAD    5504          // 43 * 128, zero-padded
#define TILE_N  128
#define MTILE   64            // rows per m-step
#define MSTEPS  2             // m-steps per CTA: CTA covers 128 batch rows
#define PITCH   144           // smem operand row pitch bytes (128B data + 16B pad)
#define OPITCHF 132           // output staging pitch in floats (128 + 4)

// ============================================================================
// Scratch (device globals; no allocation allowed)
// ============================================================================
__device__ __align__(16) __half g_Ah[BATCH * FDIM];   // fp16 inputs
__device__ __align__(16) __half g_Wh[PPAD * FDIM];    // fp16 W, rows permuted
__device__ __align__(16) float  g_bias[PPAD];

// ============================================================================
// Fused prep: fp16 convert + W row permutation (transpose fold) + bias
// ============================================================================
__global__ void prep_kernel(const float* __restrict__ A,
                            const float* __restrict__ W,
                            const float* __restrict__ b) {
    int e = blockIdx.x * blockDim.x + threadIdx.x;
    if (e < BATCH * FDIM) {
        g_Ah[e] = __float2half(A[e]);
    } else {
        int e2 = e - BATCH * FDIM;
        if (e2 < PPAD * FDIM) {
            int q = e2 >> 6, f = e2 & 63;   // q = x*67 + y
            float v = 0.0f;
            if (q < PDIM) {
                int x = q / NYC, y = q % NYC;
                v = W[(y * NXC + x) * FDIM + f];
            }
            g_Wh[e2] = __float2half(v);
            if (f == 0) {
                float bv = 0.0f;
                if (q < PDIM) {
                    int x = q / NYC, y = q % NYC;
                    bv = b[y * NXC + x];
                }
                g_bias[q] = bv;
            }
        }
    }
}

// ============================================================================
// Helpers
// ============================================================================
__device__ __forceinline__ uint32_t smem_u32(const void* p) {
    uint32_t a;
    asm("{ .reg .u64 t; cvta.to.shared.u64 t, %1; cvt.u32.u64 %0, t; }"
        : "=r"(a) : "l"(p));
    return a;
}

__device__ __forceinline__ void cpasync16(uint32_t dst, const void* src) {
    asm volatile("cp.async.cg.shared.global [%0], [%1], 16;"
                 :: "r"(dst), "l"(src));
}
#define CP_COMMIT() asm volatile("cp.async.commit_group;" ::: "memory")
#define CP_WAIT(n)  asm volatile("cp.async.wait_group %0;" :: "n"(n) : "memory")

__device__ __forceinline__ void ldm_x4(uint32_t& r0, uint32_t& r1,
                                       uint32_t& r2, uint32_t& r3, uint32_t addr) {
    asm volatile("ldmatrix.sync.aligned.m8n8.x4.shared.b16 {%0,%1,%2,%3}, [%4];"
                 : "=r"(r0), "=r"(r1), "=r"(r2), "=r"(r3) : "r"(addr));
}

__device__ __forceinline__ void mma16816(float* c, const uint32_t* a,
                                         uint32_t b0, uint32_t b1) {
    asm volatile(
        "mma.sync.aligned.m16n8k16.row.col.f32.f16.f16.f32 "
        "{%0,%1,%2,%3}, {%4,%5,%6,%7}, {%8,%9}, {%0,%1,%2,%3};"
        : "+f"(c[0]), "+f"(c[1]), "+f"(c[2]), "+f"(c[3])
        : "r"(a[0]), "r"(a[1]), "r"(a[2]), "r"(a[3]), "r"(b0), "r"(b1));
}

// ============================================================================
// GEMM: single-pass fp16, 3 CTAs/SM. Whole working set staged once; the
// k-loop runs in two halves, each holding only half the W fragment set
// (16 regs) so the kernel fits __launch_bounds__(256, 3) without spills.
// Transposed smem epilogue: contiguous 256B row chunks per STG.64.
// ============================================================================
#define SM_A     0                            // 128*144 = 18432
#define SM_W     18432                        // 128*144 = 18432
#define SM_BIAS  36864                        // 512
#define SM_O     37376                        // 64*132*4 = 33792
#define SMEM_BYTES 71168                      // x3 = 213.5 KB <= 228 KB

__global__ void __launch_bounds__(256, 3) gemm_kernel(float* __restrict__ out) {
    extern __shared__ char smem[];
    uint32_t sb = smem_u32(smem);
    int tid  = threadIdx.x;
    int lane = tid & 31;
    int wid  = tid >> 5;
    int wm   = wid & 1;        // warp row (0..1) -> 32 rows each
    int wn   = wid >> 1;       // warp col (0..3) -> 32 cols each
    int n0 = blockIdx.x * TILE_N;
    int m0 = blockIdx.y * (MTILE * MSTEPS);   // 128 rows per CTA

    // ---- stage A rows (128x128B) + W tile (128x128B) + bias, once ----
    {
        const char* gA = (const char*)(g_Ah + (size_t)m0 * FDIM);
        const char* gW = (const char*)(g_Wh + (size_t)n0 * FDIM);
        #pragma unroll
        for (int i = tid; i < 128 * 8; i += 256) {
            int r = i >> 3, ch = i & 7;
            cpasync16(sb + SM_A + r * PITCH + ch * 16, gA + r * 128 + ch * 16);
            cpasync16(sb + SM_W + r * PITCH + ch * 16, gW + r * 128 + ch * 16);
        }
        if (tid < TILE_N)
            ((float*)(smem + SM_BIAS))[tid] = g_bias[n0 + tid];
    }
    CP_COMMIT();
    CP_WAIT(0);
    __syncthreads();

    uint32_t bBase = sb + SM_W
        + (uint32_t)(wn * 32 + ((lane >> 4) << 3) + (lane & 7)) * PITCH
        + (((lane >> 3) & 1) * 16);
    uint32_t aOff = sb + SM_A
        + (uint32_t)(wm * 32 + (lane & 15)) * PITCH + ((lane >> 4) * 16);
    int g = lane >> 2, t = lane & 3;

    // per-lane epilogue constants: lane covers cols {2*lane, 2*lane+1} in each
    // 64-col phase of a row (same for every row)
    const float* sbias = (const float*)(smem + SM_BIAS);
    float2 bias2[2];
    bool pvalid[2];
    #pragma unroll
    for (int ph = 0; ph < 2; ph++) {
        bias2[ph].x = sbias[ph * 64 + 2 * lane];
        bias2[ph].y = sbias[ph * 64 + 2 * lane + 1];
        pvalid[ph] = (n0 + ph * 64 + 2 * lane) < PDIM;  // PDIM even -> pair safe
    }

    uint32_t oBase = sb + SM_O;
    uint32_t stsR = (uint32_t)(wm * 32 + g);          // + mi*16 (+8)
    uint32_t stsC = (uint32_t)(wn * 32 + 2 * t);      // + ni*8

    #pragma unroll 1
    for (int mt = 0; mt < MSTEPS; mt++) {
        float c[2][4][4];
        #pragma unroll
        for (int mi = 0; mi < 2; mi++)
            #pragma unroll
            for (int ni = 0; ni < 4; ni++)
                #pragma unroll
                for (int r = 0; r < 4; r++) c[mi][ni][r] = 0.0f;

        uint32_t aBase = aOff + (uint32_t)(mt * MTILE) * PITCH;

        // ---- k-loop in two halves; only half the W frags live at a time ----
        #pragma unroll
        for (int kh = 0; kh < 2; kh++) {
            uint32_t bF[2][2][4];          // [kk in half][nq][4] = 16 regs
            #pragma unroll
            for (int kk = 0; kk < 2; kk++)
                #pragma unroll
                for (int nq = 0; nq < 2; nq++)
                    ldm_x4(bF[kk][nq][0], bF[kk][nq][1],
                           bF[kk][nq][2], bF[kk][nq][3],
                           bBase + nq * 16 * PITCH + (kh * 2 + kk) * 32);
            #pragma unroll
            for (int kk = 0; kk < 2; kk++) {
                uint32_t aF[2][4];
                #pragma unroll
                for (int mi = 0; mi < 2; mi++)
                    ldm_x4(aF[mi][0], aF[mi][1], aF[mi][2], aF[mi][3],
                           aBase + mi * 16 * PITCH + (kh * 2 + kk) * 32);
                #pragma unroll
                for (int mi = 0; mi < 2; mi++)
                    #pragma unroll
                    for (int ni = 0; ni < 4; ni++)
                        mma16816(c[mi][ni], aF[mi],
                                 bF[kk][ni >> 1][(ni & 1) * 2],
                                 bF[kk][ni >> 1][(ni & 1) * 2 + 1]);
            }
        }

        // ---- dump accumulators to staging tile (64 x OPITCHF floats) ----
        #pragma unroll
        for (int mi = 0; mi < 2; mi++)
            #pragma unroll
            for (int ni = 0; ni < 4; ni++) {
                uint32_t r = stsR + mi * 16;
                uint32_t cadr = oBase + ((r * OPITCHF + stsC + ni * 8) << 2);
                asm volatile("st.shared.v2.f32 [%0], {%1, %2};"
                             :: "r"(cadr), "f"(c[mi][ni][0]), "f"(c[mi][ni][1])
                             : "memory");
                asm volatile("st.shared.v2.f32 [%0], {%1, %2};"
                             :: "r"(cadr + ((8u * OPITCHF) << 2)),
                                "f"(c[mi][ni][2]), "f"(c[mi][ni][3])
                             : "memory");
            }
        __syncthreads();

        // ---- contiguous row stores: warp wid handles rows wid*8..wid*8+7 ----
        int mrow = m0 + mt * MTILE;
        #pragma unroll
        for (int r = 0; r < 8; r++) {
            int lr = wid * 8 + r;                      // local row 0..63
            float* orow = out + (size_t)(mrow + lr) * PDIM + n0;
            uint32_t radr = oBase + ((uint32_t)(lr * OPITCHF + 2 * lane) << 2);
            #pragma unroll
            for (int ph = 0; ph < 2; ph++) {
                if (pvalid[ph]) {
                    float2 v;
                    asm volatile("ld.shared.v2.f32 {%0, %1}, [%2];"
                                 : "=f"(v.x), "=f"(v.y)
                                 : "r"(radr + ((ph * 64u) << 2)));
                    v.x += bias2[ph].x;
                    v.y += bias2[ph].y;
                    *(float2*)(orow + ph * 64 + 2 * lane) = v;
                }
            }
        }
        if (mt + 1 < MSTEPS) __syncthreads();  // staging reusable next m-step
    }
}

// ============================================================================
// Launch
// ============================================================================
extern "C" void kernel_launch(void* const* d_in, const int* in_sizes, int n_in,
                              void* d_out, int out_size) {
    const float* A = (const float*)d_in[0];   // [8192, 64]
    const float* W = (const float*)d_in[1];   // [5494, 64]
    const float* b = (const float*)d_in[2];   // [5494]
    float* out = (float*)d_out;               // [8192, 82, 67, 1] contiguous

    cudaFuncSetAttribute(gemm_kernel,
                         cudaFuncAttributeMaxDynamicSharedMemorySize, SMEM_BYTES);

    int prep_elems = BATCH * FDIM + PPAD * FDIM;
    prep_kernel<<<(prep_elems + 255) / 256, 256>>>(A, W, b);

    dim3 grid(PPAD / TILE_N, BATCH / (MTILE * MSTEPS));   // 43 x 64
    gemm_kernel<<<grid, 256, SMEM_BYTES>>>(out);
}